// round 12
// baseline (speedup 1.0000x reference)
#include <cuda_runtime.h>
#include <cuda_fp16.h>
#include <cstdint>
#include <math.h>

namespace {
constexpr int Bb = 128;
constexpr int Qq = 512;
constexpr int Tt = 512;
constexpr int Dd = 256;
constexpr int QT = 64;            // queries per CTA
constexpr int THREADS = 512;      // 16 warps
constexpr int TTILE = 256;        // t-cols per pass; warp owns 32
constexpr int DCH = 16;           // d-cols per K stage
constexpr int NSTAGE = 32;        // 2 passes x 16 d-chunks
constexpr int NBUF = 3;           // K pipeline depth
constexpr int QLD = 260;          // Q smem ld (1040B rows -> 16B rotation, conflict-free)
constexpr int KLD = 20;           // K smem ld (80B rows, conflict-free)
constexpr int SLD = 520;          // S fp16 ld
constexpr float SCALE = 0.0625f;  // 1/sqrt(256)

constexpr int KBUF    = 256 * KLD * 4;         // 20480 B per K buffer
constexpr int SM_Q    = 0;                     // 64*260*4 = 66560
constexpr int SM_K    = SM_Q + QT * QLD * 4;   // 3 bufs -> 61440
constexpr int SM_S    = SM_K + NBUF * KBUF;    // 64*520*2 = 66560
constexpr int SM_ROW  = SM_S + QT * SLD * 2;
constexpr int SM_RINV = SM_ROW + 256;
constexpr int SMEM_BYTES = SM_RINV + 256;      // ~195.5 KB -> 1 CTA/SM
}  // namespace

__device__ float g_partial[Bb * 8 * Tt];      // per-(batch,qtile) colsum partials
__device__ float g_pool[Bb * 4 * Dd];         // per-(batch,tslice) pooled partials

__device__ __forceinline__ uint32_t smem_u32(const void* p) {
    uint32_t a;
    asm("{ .reg .u64 t; cvta.to.shared.u64 t, %1; cvt.u32.u64 %0, t; }" : "=r"(a) : "l"(p));
    return a;
}
__device__ __forceinline__ float to_tf32(float x) {
    float y;
    asm("cvt.rna.tf32.f32 %0, %1;" : "=f"(y) : "f"(x));
    return y;
}
// PTX m16n8k8 tf32 mma; fragment layouts are architecturally specified.
__device__ __forceinline__ void mma_tf32(float* c, const uint32_t* a, uint32_t b0,
                                         uint32_t b1) {
    asm volatile(
        "mma.sync.aligned.m16n8k8.row.col.f32.tf32.tf32.f32 "
        "{%0,%1,%2,%3}, {%4,%5,%6,%7}, {%8,%9}, {%0,%1,%2,%3};"
        : "+f"(c[0]), "+f"(c[1]), "+f"(c[2]), "+f"(c[3])
        : "r"(a[0]), "r"(a[1]), "r"(a[2]), "r"(a[3]), "r"(b0), "r"(b1));
}

// cp.async one K chunk: 256 t-rows x 16 d-cols into buf stage%NBUF.
__device__ __forceinline__ void issue_stage(uint32_t sb, const float* __restrict__ Kg,
                                            int stage, int tid) {
    const int buf = stage % NBUF, p = stage >> 4, dc = stage & 15;
    const float* base = Kg + (size_t)p * TTILE * Dd + dc * DCH;
    const uint32_t dbase = sb + SM_K + buf * KBUF;
#pragma unroll
    for (int it = 0; it < 4; ++it) {
        int c = tid + it * THREADS;  // 0..2047
        int row = c >> 3, q = c & 7;
        uint32_t dst = dbase + (uint32_t)(row * KLD + q * 2) * 4;
        const float* g = base + (size_t)row * Dd + q * 2;
        asm volatile("cp.async.ca.shared.global [%0], [%1], 8;" :: "r"(dst), "l"(g));
    }
    asm volatile("cp.async.commit_group;" ::: "memory");
}

// Per CTA: (batch, 64-query tile). S = softmax rows of scale*Q.K^T; write
// weight column-sum partial to g_partial (no atomics).
__global__ void __launch_bounds__(THREADS, 1)
score_kernel(const float* __restrict__ inputs, const float* __restrict__ query) {
    extern __shared__ char smem[];
    const uint32_t sb = smem_u32(smem);
    const int tid = threadIdx.x, wid = tid >> 5, lane = tid & 31;
    const int wq = wid >> 3;   // q-half (32 rows)
    const int wt = wid & 7;    // 32 t-cols within pass
    const int g = lane >> 2, tg = lane & 3;
    const int batch = blockIdx.x >> 3;
    const int q0 = (blockIdx.x & 7) * QT;

    const float* Qg = query + ((size_t)batch * Qq + q0) * Dd;
    const float* Kg = inputs + (size_t)batch * Tt * Dd;

    float* Qs = (float*)(smem + SM_Q);
    float* rowsum = (float*)(smem + SM_ROW);
    float* rinv = (float*)(smem + SM_RINV);
    __half* Sh = (__half*)(smem + SM_S);

    issue_stage(sb, Kg, 0, tid);  // pipeline prologue: 2 stages in flight
    issue_stage(sb, Kg, 1, tid);

    if (tid < QT) rowsum[tid] = 0.0f;

    // Stage Q (scale folded, tf32-rounded), 64x256 -> 4096 float4
#pragma unroll
    for (int it = 0; it < 8; ++it) {
        int i = tid + it * THREADS;
        int r = i >> 6, c4 = i & 63;
        float4 v = ((const float4*)Qg)[r * 64 + c4];
        float* q = Qs + r * QLD + c4 * 4;
        q[0] = to_tf32(v.x * SCALE);
        q[1] = to_tf32(v.y * SCALE);
        q[2] = to_tf32(v.z * SCALE);
        q[3] = to_tf32(v.w * SCALE);
    }

    float acc[2][4][4];  // [mi][ni][c]

    for (int stage = 0; stage < NSTAGE; ++stage) {
        const int buf = stage % NBUF, p = stage >> 4, dc = stage & 15;
        // allow 1 group in flight -> stage `stage` is complete
        asm volatile("cp.async.wait_group 1;" ::: "memory");
        __syncthreads();
        if (stage + 2 < NSTAGE) issue_stage(sb, Kg, stage + 2, tid);

        if (dc == 0) {
#pragma unroll
            for (int mi = 0; mi < 2; ++mi)
#pragma unroll
                for (int ni = 0; ni < 4; ++ni)
#pragma unroll
                    for (int c = 0; c < 4; ++c) acc[mi][ni][c] = 0.0f;
        }
        const float* Kb = (const float*)(smem + SM_K + buf * KBUF);

#pragma unroll
        for (int ks = 0; ks < 2; ++ks) {
            const int col = dc * DCH + ks * 8 + tg;
            uint32_t a[2][4];
#pragma unroll
            for (int mi = 0; mi < 2; ++mi) {
                const uint32_t* Ar =
                    (const uint32_t*)(Qs + (wq * 32 + mi * 16 + g) * QLD + col);
                a[mi][0] = Ar[0];
                a[mi][1] = Ar[8 * QLD];
                a[mi][2] = Ar[4];
                a[mi][3] = Ar[8 * QLD + 4];
            }
#pragma unroll
            for (int ni = 0; ni < 4; ++ni) {
                const uint32_t* Br =
                    (const uint32_t*)(Kb + (wt * 32 + ni * 8 + g) * KLD + ks * 8 + tg);
                uint32_t b0 = Br[0], b1 = Br[4];
                mma_tf32(acc[0][ni], a[0], b0, b1);
                mma_tf32(acc[1][ni], a[1], b0, b1);
            }
        }

        if (dc == 15) {
            // Register-direct epilogue for pass p: exp -> S (fp16), rowsum partials.
            float rsum[4] = {0.0f, 0.0f, 0.0f, 0.0f};
            const int tb = p * TTILE + wt * 32;
#pragma unroll
            for (int mi = 0; mi < 2; ++mi) {
                const int r = wq * 32 + mi * 16 + g;
#pragma unroll
                for (int ni = 0; ni < 4; ++ni) {
                    float e0 = __expf(acc[mi][ni][0]);
                    float e1 = __expf(acc[mi][ni][1]);
                    float e2 = __expf(acc[mi][ni][2]);
                    float e3 = __expf(acc[mi][ni][3]);
                    rsum[mi * 2 + 0] += e0 + e1;
                    rsum[mi * 2 + 1] += e2 + e3;
                    const int c = tb + ni * 8 + tg * 2;
                    *(__half2*)(Sh + r * SLD + c) = __floats2half2_rn(e0, e1);
                    *(__half2*)(Sh + (r + 8) * SLD + c) = __floats2half2_rn(e2, e3);
                }
            }
#pragma unroll
            for (int j = 0; j < 4; ++j) {
                rsum[j] += __shfl_xor_sync(0xffffffffu, rsum[j], 1);
                rsum[j] += __shfl_xor_sync(0xffffffffu, rsum[j], 2);
            }
            if (tg == 0) {
                atomicAdd(&rowsum[wq * 32 + g], rsum[0]);
                atomicAdd(&rowsum[wq * 32 + g + 8], rsum[1]);
                atomicAdd(&rowsum[wq * 32 + 16 + g], rsum[2]);
                atomicAdd(&rowsum[wq * 32 + 24 + g], rsum[3]);
            }
        }
    }
    __syncthreads();
    if (tid < QT) rinv[tid] = 1.0f / rowsum[tid];
    __syncthreads();

    // Column sums of normalized weights -> g_partial (one t per thread)
    const int t = tid;
    float s = 0.0f;
#pragma unroll 8
    for (int r = 0; r < QT; ++r) s += __half2float(Sh[r * SLD + t]) * rinv[r];
    g_partial[(size_t)blockIdx.x * Tt + t] = s;
}

// Stage 1 pool: (batch, t-slice of 128): g_pool[b,s,d] = sum_t c_t * V[t,d]
__global__ void __launch_bounds__(256)
pool_partial_kernel(const float* __restrict__ inputs) {
    __shared__ float c[128];
    const int b = blockIdx.x >> 2;
    const int s = blockIdx.x & 3;
    const int t0 = s * 128;
    if (threadIdx.x < 128) {
        float v = 0.0f;
#pragma unroll
        for (int j = 0; j < 8; ++j)
            v += g_partial[((size_t)b * 8 + j) * Tt + t0 + threadIdx.x];
        c[threadIdx.x] = v;
    }
    __syncthreads();

    const float* V = inputs + ((size_t)b * Tt + t0) * Dd;
    const int d = threadIdx.x;
    float a0 = 0.0f, a1 = 0.0f, a2 = 0.0f, a3 = 0.0f;
#pragma unroll 4
    for (int t = 0; t < 128; t += 4) {
        a0 += c[t + 0] * V[(size_t)(t + 0) * Dd + d];
        a1 += c[t + 1] * V[(size_t)(t + 1) * Dd + d];
        a2 += c[t + 2] * V[(size_t)(t + 2) * Dd + d];
        a3 += c[t + 3] * V[(size_t)(t + 3) * Dd + d];
    }
    g_pool[(size_t)blockIdx.x * Dd + d] = (a0 + a1) + (a2 + a3);
}

// Stage 2 pool: out[b,d] = sum_s g_pool[b,s,d]
__global__ void __launch_bounds__(256)
pool_reduce_kernel(float* __restrict__ out) {
    const int b = blockIdx.x, d = threadIdx.x;
    float s = 0.0f;
#pragma unroll
    for (int j = 0; j < 4; ++j) s += g_pool[((size_t)b * 4 + j) * Dd + d];
    out[b * Dd + d] = s;
}

extern "C" void kernel_launch(void* const* d_in, const int* in_sizes, int n_in,
                              void* d_out, int out_size) {
    const float* inputs = (const float*)d_in[0];  // [B, T, D]
    const float* query  = (const float*)d_in[1];  // [B, Q, D]
    float* out = (float*)d_out;                   // [B, D]

    cudaFuncSetAttribute(score_kernel,
                         cudaFuncAttributeMaxDynamicSharedMemorySize, SMEM_BYTES);

    score_kernel<<<Bb * (Qq / QT), THREADS, SMEM_BYTES>>>(inputs, query);
    pool_partial_kernel<<<Bb * 4, 256>>>(inputs);
    pool_reduce_kernel<<<Bb, 256>>>(out);
}